// round 1
// baseline (speedup 1.0000x reference)
#include <cuda_runtime.h>

#define B_  16384
#define L_  50
#define D_  128
#define SMS 132   // padded smem stride (floats), float4-aligned

// 8 MB scratch for the pooled history embedding [B, D]
__device__ float g_his[B_ * D_];

// ---------------------------------------------------------------------------
// Kernel 1: masked gather-sum. One warp per batch row, float4 per lane
// (lane covers 4 of the 128 dims -> 512B fully-coalesced row loads).
// ---------------------------------------------------------------------------
__global__ __launch_bounds__(256) void gather_kernel(
    const int*    __restrict__ entities,
    const int*    __restrict__ history,
    const int*    __restrict__ hist_len,
    const float4* __restrict__ embv)    // emb viewed as float4, row stride 32
{
    const int warp = threadIdx.x >> 5;
    const int lane = threadIdx.x & 31;
    const int b    = (blockIdx.x << 3) + warp;

    __shared__ int sh_idx[8][52];

    const int n = hist_len[b];
    for (int l = lane; l < n; l += 32)
        sh_idx[warp][l] = history[b * L_ + l];
    __syncwarp();

    float4 a0 = make_float4(0.f, 0.f, 0.f, 0.f);
    float4 a1 = a0, a2 = a0, a3 = a0;

    int l = 0;
    // unroll-4 with independent accumulators -> 4 outstanding 512B loads/warp
    for (; l + 4 <= n; l += 4) {
        const long i0 = sh_idx[warp][l + 0];
        const long i1 = sh_idx[warp][l + 1];
        const long i2 = sh_idx[warp][l + 2];
        const long i3 = sh_idx[warp][l + 3];
        float4 v0 = __ldg(&embv[i0 * 32 + lane]);
        float4 v1 = __ldg(&embv[i1 * 32 + lane]);
        float4 v2 = __ldg(&embv[i2 * 32 + lane]);
        float4 v3 = __ldg(&embv[i3 * 32 + lane]);
        a0.x += v0.x; a0.y += v0.y; a0.z += v0.z; a0.w += v0.w;
        a1.x += v1.x; a1.y += v1.y; a1.z += v1.z; a1.w += v1.w;
        a2.x += v2.x; a2.y += v2.y; a2.z += v2.z; a2.w += v2.w;
        a3.x += v3.x; a3.y += v3.y; a3.z += v3.z; a3.w += v3.w;
    }
    for (; l < n; l++) {
        const long i0 = sh_idx[warp][l];
        float4 v0 = __ldg(&embv[i0 * 32 + lane]);
        a0.x += v0.x; a0.y += v0.y; a0.z += v0.z; a0.w += v0.w;
    }

    float4 acc;
    acc.x = (a0.x + a1.x) + (a2.x + a3.x);
    acc.y = (a0.y + a1.y) + (a2.y + a3.y);
    acc.z = (a0.z + a1.z) + (a2.z + a3.z);
    acc.w = (a0.w + a1.w) + (a2.w + a3.w);

    if (n == 0)
        acc = __ldg(&embv[(long)entities[b] * 32 + lane]);

    ((float4*)g_his)[b * 32 + lane] = acc;
}

// ---------------------------------------------------------------------------
// Kernel 2: out = his @ W^T + bias. 128x128 tile per CTA, full K=128 in smem,
// 256 threads, 8x8 register microtile. his and W staged transposed ([k][i])
// so the inner loop does conflict-free LDS.128.
// ---------------------------------------------------------------------------
__global__ __launch_bounds__(256) void linear_kernel(
    const float* __restrict__ W,
    const float* __restrict__ bias,
    float*       __restrict__ out)
{
    extern __shared__ float sm[];
    float* hsT = sm;                 // [128][SMS]  (k-major, i inner)
    float* wsT = sm + 128 * SMS;     // [128][SMS]  (k-major, j inner)

    const int tid  = threadIdx.x;
    const int row0 = blockIdx.x * 128;

    const float4* hisv = (const float4*)g_his;
    const float4* Wv   = (const float4*)W;

    // Stage + transpose: 128 rows x 32 float4 each for his-tile and W.
    for (int t = tid; t < 128 * 32; t += 256) {
        const int i  = t >> 5;
        const int kv = t & 31;
        float4 v = hisv[(long)(row0 + i) * 32 + kv];
        hsT[(kv * 4 + 0) * SMS + i] = v.x;
        hsT[(kv * 4 + 1) * SMS + i] = v.y;
        hsT[(kv * 4 + 2) * SMS + i] = v.z;
        hsT[(kv * 4 + 3) * SMS + i] = v.w;
        float4 w = Wv[(long)i * 32 + kv];
        wsT[(kv * 4 + 0) * SMS + i] = w.x;
        wsT[(kv * 4 + 1) * SMS + i] = w.y;
        wsT[(kv * 4 + 2) * SMS + i] = w.z;
        wsT[(kv * 4 + 3) * SMS + i] = w.w;
    }
    __syncthreads();

    const int tx = tid & 15;        // 16 threads over j
    const int ty = tid >> 4;        // 16 threads over i
    const int j0 = tx * 8;
    const int i0 = ty * 8;

    float acc[8][8];
#pragma unroll
    for (int ii = 0; ii < 8; ii++)
#pragma unroll
        for (int jj = 0; jj < 8; jj++)
            acc[ii][jj] = 0.f;

#pragma unroll 8
    for (int k = 0; k < 128; k++) {
        float a[8], bb[8];
        *(float4*)&a[0]  = *(const float4*)&hsT[k * SMS + i0];
        *(float4*)&a[4]  = *(const float4*)&hsT[k * SMS + i0 + 4];
        *(float4*)&bb[0] = *(const float4*)&wsT[k * SMS + j0];
        *(float4*)&bb[4] = *(const float4*)&wsT[k * SMS + j0 + 4];
#pragma unroll
        for (int ii = 0; ii < 8; ii++)
#pragma unroll
            for (int jj = 0; jj < 8; jj++)
                acc[ii][jj] = fmaf(a[ii], bb[jj], acc[ii][jj]);
    }

    float bj[8];
    *(float4*)&bj[0] = ((const float4*)bias)[tx * 2 + 0];
    *(float4*)&bj[4] = ((const float4*)bias)[tx * 2 + 1];

#pragma unroll
    for (int ii = 0; ii < 8; ii++) {
        float4 o0, o1;
        o0.x = acc[ii][0] + bj[0]; o0.y = acc[ii][1] + bj[1];
        o0.z = acc[ii][2] + bj[2]; o0.w = acc[ii][3] + bj[3];
        o1.x = acc[ii][4] + bj[4]; o1.y = acc[ii][5] + bj[5];
        o1.z = acc[ii][6] + bj[6]; o1.w = acc[ii][7] + bj[7];
        float* orow = out + (long)(row0 + i0 + ii) * 128 + j0;
        *(float4*)&orow[0] = o0;
        *(float4*)&orow[4] = o1;
    }
}

// ---------------------------------------------------------------------------
extern "C" void kernel_launch(void* const* d_in, const int* in_sizes, int n_in,
                              void* d_out, int out_size)
{
    const int*   entities = (const int*)d_in[0];
    const int*   history  = (const int*)d_in[1];
    const int*   hist_len = (const int*)d_in[2];
    const float* emb      = (const float*)d_in[3];
    const float* W        = (const float*)d_in[4];
    const float* bias     = (const float*)d_in[5];
    float*       out      = (float*)d_out;

    gather_kernel<<<B_ / 8, 256>>>(entities, history, hist_len,
                                   (const float4*)emb);

    const size_t smem = (size_t)2 * 128 * SMS * sizeof(float);
    cudaFuncSetAttribute(linear_kernel,
                         cudaFuncAttributeMaxDynamicSharedMemorySize,
                         (int)smem);
    linear_kernel<<<B_ / 128, 256, smem>>>(W, bias, out);
}